// round 2
// baseline (speedup 1.0000x reference)
#include <cuda_runtime.h>
#include <cstdint>

// Problem constants
#define Bc 4
#define Nc 8192
#define Fc 64
#define Sc 2048
#define Kc 16
#define Cc 128
#define MTOT (Bc*Sc*Kc)          // 131072 rows through the MLP
#define GBLKS (MTOT/128)         // 1024 gemm blocks

// -------- scratch (static device allocations; no cudaMalloc allowed) --------
__device__ float g_h0[(size_t)MTOT*Cc];   // 64 MB, pre-BN layer0 output
__device__ float g_h1[(size_t)MTOT*Cc];   // 64 MB, pre-BN layer1 output
__device__ int   g_knn[Bc*Sc*Kc];
__device__ float g_part0[GBLKS*Cc*2];
__device__ float g_part1[GBLKS*Cc*2];
__device__ float g_aff0[2*Cc];            // [a..., b...] affine for relu(bn)
__device__ float g_aff1[2*Cc];

// ============================================================================
// 1) Farthest point sampling. One CTA per batch. 512 thr x 16 pts/thread.
//    Exact FP op-order replication of: d=((dx*dx+dy*dy)+dz*dz);
//    min_d=min(min_d,d); argmax first-index tie-break.
// ============================================================================
#define FPS_SMEM (3*Nc*4 + 2*16*8)

__global__ __launch_bounds__(512,1) void fps_kernel(const float* __restrict__ xyz,
                                                    float* __restrict__ out)
{
    const int b = blockIdx.x;
    extern __shared__ float smem_f[];
    float* X = smem_f;
    float* Y = smem_f + Nc;
    float* Z = smem_f + 2*Nc;
    unsigned long long* part = (unsigned long long*)(smem_f + 3*Nc);

    const float* base = xyz + (size_t)b*Nc*3;
    float* oxyz = out + (size_t)b*Sc*3;
    const int t = threadIdx.x;
    const int lane = t & 31, wid = t >> 5;

    float px[16], py[16], pz[16], md[16];
#pragma unroll
    for (int j = 0; j < 16; j++) {
        int p = t*16 + j;
        float x = base[p*3+0], y = base[p*3+1], z = base[p*3+2];
        px[j]=x; py[j]=y; pz[j]=z; md[j]=1e10f;
        X[p]=x; Y[p]=y; Z[p]=z;
    }
    __syncthreads();

    float cx = X[0], cy = Y[0], cz = Z[0];

    for (int s = 0; s < Sc; s++) {
        if (t == 0) {
            oxyz[s*3+0]=cx; oxyz[s*3+1]=cy; oxyz[s*3+2]=cz;
        }
        if (s == Sc-1) break;

        float best = -1.0f; int bidx = 0;
#pragma unroll
        for (int j = 0; j < 16; j++) {
            float dx = __fsub_rn(px[j], cx);
            float dy = __fsub_rn(py[j], cy);
            float dz = __fsub_rn(pz[j], cz);
            float d  = __fadd_rn(__fadd_rn(__fmul_rn(dx,dx), __fmul_rn(dy,dy)),
                                 __fmul_rn(dz,dz));
            float m = fminf(md[j], d);
            md[j] = m;
            if (m > best) { best = m; bidx = t*16 + j; }   // strict > keeps earliest idx
        }
        // pack: value bits high (non-negative float -> monotone in uint),
        // ~idx low so that equal values resolve to smaller index under max.
        unsigned long long key =
            ((unsigned long long)__float_as_uint(best) << 32) | (unsigned)(~bidx);
#pragma unroll
        for (int o = 16; o; o >>= 1) {
            unsigned long long ok = __shfl_xor_sync(0xffffffffu, key, o);
            if (ok > key) key = ok;
        }
        unsigned long long* pb = part + (s & 1)*16;   // double buffer, 1 bar/iter
        if (lane == 0) pb[wid] = key;
        __syncthreads();
        key = pb[lane & 15];
#pragma unroll
        for (int o = 8; o; o >>= 1) {
            unsigned long long ok = __shfl_xor_sync(0xffffffffu, key, o);
            if (ok > key) key = ok;
        }
        int w = (int)(~(unsigned)key);
        cx = X[w]; cy = Y[w]; cz = Z[w];
    }
}

// ============================================================================
// 2) Brute-force KNN (K=16). 64 queries per CTA, whole cloud in SMEM.
//    d2 = (|q|^2 + |p|^2) - 2*q.p   (expanded form, exact ref op order)
//    Stable top-16: strict-< threshold, insertion stops at equality.
// ============================================================================
#define KNN_SMEM (Nc*16)

__global__ __launch_bounds__(64,1) void knn_kernel(const float* __restrict__ xyz,
                                                   const float* __restrict__ newxyz)
{
    extern __shared__ float smem_f[];
    float4* tile = (float4*)smem_f;
    const int blk = blockIdx.x;      // 128 blocks = 4 batches * 32
    const int b = blk >> 5;
    const int qbase = (blk & 31) * 64;
    const float* base = xyz + (size_t)b*Nc*3;

    for (int p = threadIdx.x; p < Nc; p += 64) {
        float x = base[p*3], y = base[p*3+1], z = base[p*3+2];
        float sq = __fadd_rn(__fadd_rn(__fmul_rn(x,x), __fmul_rn(y,y)), __fmul_rn(z,z));
        tile[p] = make_float4(x, y, z, sq);
    }
    __syncthreads();

    const int qi = b*Sc + qbase + threadIdx.x;
    float qx = newxyz[qi*3], qy = newxyz[qi*3+1], qz = newxyz[qi*3+2];
    float sqq = __fadd_rn(__fadd_rn(__fmul_rn(qx,qx), __fmul_rn(qy,qy)), __fmul_rn(qz,qz));

    float dist[Kc]; int ids[Kc];
#pragma unroll
    for (int i = 0; i < Kc; i++) { dist[i] = 3.4e38f; ids[i] = 0; }
    float kth = 3.4e38f;

    for (int p = 0; p < Nc; p++) {
        float4 v = tile[p];
        float dot = __fadd_rn(__fadd_rn(__fmul_rn(qx,v.x), __fmul_rn(qy,v.y)),
                              __fmul_rn(qz,v.z));
        float d2 = __fsub_rn(__fadd_rn(sqq, v.w), __fadd_rn(dot, dot)); // 2*dot exact
        if (d2 < kth) {
            int j = Kc-1;
            while (j > 0 && dist[j-1] > d2) {   // stops at equality -> stable order
                dist[j] = dist[j-1]; ids[j] = ids[j-1]; j--;
            }
            dist[j] = d2; ids[j] = p;
            kth = dist[Kc-1];
        }
    }
#pragma unroll
    for (int i = 0; i < Kc; i++) g_knn[qi*Kc + i] = ids[i];
}

// ============================================================================
// 3) Gather + layer0 GEMM (M=131072, N=128, K=67) + BN-stat partials.
//    128x128 tile, 256 threads, 8x8 microtiles.
// ============================================================================
#define G0_SMEM (2*68*128*4)

__global__ __launch_bounds__(256,1) void gemm0_kernel(const float* __restrict__ xyz,
                                                      const float* __restrict__ feat,
                                                      const float* __restrict__ w0,
                                                      const float* __restrict__ b0,
                                                      const float* __restrict__ newxyz)
{
    extern __shared__ float smem_f[];
    float (*As)[128] = (float(*)[128])smem_f;                 // [68][128]  k-major
    float (*Ws)[128] = (float(*)[128])(smem_f + 68*128);      // [68][128]
    const int t = threadIdx.x;
    const int blk = blockIdx.x;

    for (int i = t; i < Cc*67; i += 256) {                    // w0: [C][67]
        int c = i / 67, f = i - c*67;
        Ws[f][c] = w0[i];
    }
    {
        int m = t & 127, half = t >> 7;
        int R = blk*128 + m;
        int bs = R >> 4;
        int b = bs >> 11;
        int nid = g_knn[R];
        const float* frow = feat + ((size_t)b*Nc + nid)*Fc;
        if (half == 0) {
            const float* prow = xyz + ((size_t)b*Nc + nid)*3;
            As[0][m] = __fsub_rn(prow[0], newxyz[bs*3+0]);
            As[1][m] = __fsub_rn(prow[1], newxyz[bs*3+1]);
            As[2][m] = __fsub_rn(prow[2], newxyz[bs*3+2]);
            for (int f = 0; f < 32; f += 4) {
                float4 v = *(const float4*)(frow + f);
                As[3+f][m]=v.x; As[4+f][m]=v.y; As[5+f][m]=v.z; As[6+f][m]=v.w;
            }
        } else {
            for (int f = 32; f < 64; f += 4) {
                float4 v = *(const float4*)(frow + f);
                As[3+f][m]=v.x; As[4+f][m]=v.y; As[5+f][m]=v.z; As[6+f][m]=v.w;
            }
        }
    }
    __syncthreads();

    const int tn = t & 15, tm = t >> 4;
    float acc[8][8];
#pragma unroll
    for (int i = 0; i < 8; i++)
#pragma unroll
        for (int j = 0; j < 8; j++) acc[i][j] = 0.f;

    for (int kk = 0; kk < 67; kk++) {
        float a[8], w[8];
        *(float4*)(a)   = *(const float4*)&As[kk][tm*8];
        *(float4*)(a+4) = *(const float4*)&As[kk][tm*8+4];
        *(float4*)(w)   = *(const float4*)&Ws[kk][tn*8];
        *(float4*)(w+4) = *(const float4*)&Ws[kk][tn*8+4];
#pragma unroll
        for (int i = 0; i < 8; i++)
#pragma unroll
            for (int j = 0; j < 8; j++) acc[i][j] = fmaf(a[i], w[j], acc[i][j]);
    }

    float bb[8], sum[8], ssq[8];
#pragma unroll
    for (int j = 0; j < 8; j++) { bb[j] = b0[tn*8+j]; sum[j]=0.f; ssq[j]=0.f; }
#pragma unroll
    for (int i = 0; i < 8; i++) {
        size_t row = (size_t)blk*128 + tm*8 + i;
        float v[8];
#pragma unroll
        for (int j = 0; j < 8; j++) {
            v[j] = __fadd_rn(acc[i][j], bb[j]);
            sum[j] += v[j];
            ssq[j] = fmaf(v[j], v[j], ssq[j]);
        }
        *(float4*)&g_h0[row*Cc + tn*8]     = make_float4(v[0],v[1],v[2],v[3]);
        *(float4*)&g_h0[row*Cc + tn*8 + 4] = make_float4(v[4],v[5],v[6],v[7]);
    }
    __syncthreads();
    float* st = smem_f;                     // reuse: [128ch][16tm] sum, +2048 ssq
#pragma unroll
    for (int j = 0; j < 8; j++) {
        st[(tn*8+j)*16 + tm]        = sum[j];
        st[2048 + (tn*8+j)*16 + tm] = ssq[j];
    }
    __syncthreads();
    if (t < Cc) {
        float s = 0.f, q = 0.f;
        for (int r = 0; r < 16; r++) { s += st[t*16+r]; q += st[2048 + t*16 + r]; }
        g_part0[((size_t)blk*Cc + t)*2]   = s;
        g_part0[((size_t)blk*Cc + t)*2+1] = q;
    }
}

// ============================================================================
// 4) BN stat reduce -> affine (deterministic, fp64 accumulation)
// ============================================================================
__global__ void stats_kernel(int layer, const float* __restrict__ gamma,
                             const float* __restrict__ beta)
{
    const float* part = layer ? g_part1 : g_part0;
    float* aff = layer ? g_aff1 : g_aff0;
    int c = threadIdx.x;
    double s = 0.0, q = 0.0;
    for (int i = 0; i < GBLKS; i++) {
        s += (double)part[((size_t)i*Cc + c)*2];
        q += (double)part[((size_t)i*Cc + c)*2 + 1];
    }
    double cnt = (double)MTOT;
    double mean = s / cnt;
    double var = q / cnt - mean*mean;
    float a = gamma[c] * (float)(1.0 / sqrt(var + 1e-5));
    aff[c] = a;
    aff[Cc + c] = __fsub_rn(beta[c], (float)mean * a);
}

// ============================================================================
// 5) Layer1 GEMM (K=128): A = relu(affine0(h0)), W = w1. + BN1 partials.
// ============================================================================
#define G1_SMEM (2*128*128*4)

__global__ __launch_bounds__(256,1) void gemm1_kernel(const float* __restrict__ w1,
                                                      const float* __restrict__ b1)
{
    extern __shared__ float smem_f[];
    float (*As)[128] = (float(*)[128])smem_f;                 // [128][128]
    float (*Ws)[128] = (float(*)[128])(smem_f + 128*128);
    const int t = threadIdx.x;
    const int blk = blockIdx.x;

    for (int i = t; i < Cc*Cc; i += 256) {                    // w1: [C][C]
        int c = i >> 7, f = i & 127;
        Ws[f][c] = w1[i];
    }
    {
        int m = t & 127, half = t >> 7;
        size_t R = (size_t)blk*128 + m;
        const float* hrow = g_h0 + R*Cc + half*64;
        for (int f = 0; f < 64; f += 4) {
            float4 v = *(const float4*)(hrow + f);
            int fg = half*64 + f;
            As[fg+0][m] = fmaxf(fmaf(g_aff0[fg+0], v.x, g_aff0[Cc+fg+0]), 0.f);
            As[fg+1][m] = fmaxf(fmaf(g_aff0[fg+1], v.y, g_aff0[Cc+fg+1]), 0.f);
            As[fg+2][m] = fmaxf(fmaf(g_aff0[fg+2], v.z, g_aff0[Cc+fg+2]), 0.f);
            As[fg+3][m] = fmaxf(fmaf(g_aff0[fg+3], v.w, g_aff0[Cc+fg+3]), 0.f);
        }
    }
    __syncthreads();

    const int tn = t & 15, tm = t >> 4;
    float acc[8][8];
#pragma unroll
    for (int i = 0; i < 8; i++)
#pragma unroll
        for (int j = 0; j < 8; j++) acc[i][j] = 0.f;

    for (int kk = 0; kk < Cc; kk++) {
        float a[8], w[8];
        *(float4*)(a)   = *(const float4*)&As[kk][tm*8];
        *(float4*)(a+4) = *(const float4*)&As[kk][tm*8+4];
        *(float4*)(w)   = *(const float4*)&Ws[kk][tn*8];
        *(float4*)(w+4) = *(const float4*)&Ws[kk][tn*8+4];
#pragma unroll
        for (int i = 0; i < 8; i++)
#pragma unroll
            for (int j = 0; j < 8; j++) acc[i][j] = fmaf(a[i], w[j], acc[i][j]);
    }

    float bb[8], sum[8], ssq[8];
#pragma unroll
    for (int j = 0; j < 8; j++) { bb[j] = b1[tn*8+j]; sum[j]=0.f; ssq[j]=0.f; }
#pragma unroll
    for (int i = 0; i < 8; i++) {
        size_t row = (size_t)blk*128 + tm*8 + i;
        float v[8];
#pragma unroll
        for (int j = 0; j < 8; j++) {
            v[j] = __fadd_rn(acc[i][j], bb[j]);
            sum[j] += v[j];
            ssq[j] = fmaf(v[j], v[j], ssq[j]);
        }
        *(float4*)&g_h1[row*Cc + tn*8]     = make_float4(v[0],v[1],v[2],v[3]);
        *(float4*)&g_h1[row*Cc + tn*8 + 4] = make_float4(v[4],v[5],v[6],v[7]);
    }
    __syncthreads();
    float* st = smem_f;
#pragma unroll
    for (int j = 0; j < 8; j++) {
        st[(tn*8+j)*16 + tm]        = sum[j];
        st[2048 + (tn*8+j)*16 + tm] = ssq[j];
    }
    __syncthreads();
    if (t < Cc) {
        float s = 0.f, q = 0.f;
        for (int r = 0; r < 16; r++) { s += st[t*16+r]; q += st[2048 + t*16 + r]; }
        g_part1[((size_t)blk*Cc + t)*2]   = s;
        g_part1[((size_t)blk*Cc + t)*2+1] = q;
    }
}

// ============================================================================
// 6) relu(affine1(h1)) then max over K -> new_features
// ============================================================================
__global__ __launch_bounds__(256) void final_kernel(float* __restrict__ out)
{
    int gid = blockIdx.x*256 + threadIdx.x;     // B*S*C = 1,048,576
    int c = gid & 127, bs = gid >> 7;
    float a = g_aff1[c], b = g_aff1[Cc + c];
    float m = -3.4e38f;
#pragma unroll
    for (int k = 0; k < Kc; k++) {
        float h = g_h1[((size_t)(bs*Kc + k))*Cc + c];
        float v = fmaxf(fmaf(a, h, b), 0.f);
        m = fmaxf(m, v);
    }
    out[Bc*Sc*3 + gid] = m;
}

// ============================================================================
extern "C" void kernel_launch(void* const* d_in, const int* in_sizes, int n_in,
                              void* d_out, int out_size)
{
    const float* xyz  = (const float*)d_in[0];
    const float* feat = (const float*)d_in[1];
    const float* w0   = (const float*)d_in[2];
    const float* b0   = (const float*)d_in[3];
    const float* g0   = (const float*)d_in[4];
    const float* be0  = (const float*)d_in[5];
    const float* w1   = (const float*)d_in[6];
    const float* b1   = (const float*)d_in[7];
    const float* g1   = (const float*)d_in[8];
    const float* be1  = (const float*)d_in[9];
    float* out = (float*)d_out;

    cudaFuncSetAttribute(fps_kernel,   cudaFuncAttributeMaxDynamicSharedMemorySize, FPS_SMEM);
    cudaFuncSetAttribute(knn_kernel,   cudaFuncAttributeMaxDynamicSharedMemorySize, KNN_SMEM);
    cudaFuncSetAttribute(gemm0_kernel, cudaFuncAttributeMaxDynamicSharedMemorySize, G0_SMEM);
    cudaFuncSetAttribute(gemm1_kernel, cudaFuncAttributeMaxDynamicSharedMemorySize, G1_SMEM);

    fps_kernel  <<<Bc, 512, FPS_SMEM>>>(xyz, out);
    knn_kernel  <<<128, 64, KNN_SMEM>>>(xyz, out);
    gemm0_kernel<<<GBLKS, 256, G0_SMEM>>>(xyz, feat, w0, b0, out);
    stats_kernel<<<1, Cc>>>(0, g0, be0);
    gemm1_kernel<<<GBLKS, 256, G1_SMEM>>>(w1, b1);
    stats_kernel<<<1, Cc>>>(1, g1, be1);
    final_kernel<<<(Bc*Sc*Cc)/256, 256>>>(out);
}

// round 3
// speedup vs baseline: 1.1195x; 1.1195x over previous
#include <cuda_runtime.h>
#include <cstdint>

// Problem constants
#define Bc 4
#define Nc 8192
#define Fc 64
#define Sc 2048
#define Kc 16
#define Cc 128
#define MTOT (Bc*Sc*Kc)          // 131072 rows through the MLP
#define GBLKS (MTOT/128)         // 1024 gemm blocks
#define FULLM 0xffffffffu

typedef unsigned long long ull;

// -------- scratch (static device allocations; no cudaMalloc allowed) --------
__device__ float g_h0[(size_t)MTOT*Cc];   // 64 MB, pre-BN layer0 output
__device__ float g_h1[(size_t)MTOT*Cc];   // 64 MB, pre-BN layer1 output
__device__ int   g_knn[Bc*Sc*Kc];
__device__ float g_partS0[Cc*GBLKS];      // [c][blk] coalesced for stats
__device__ float g_partQ0[Cc*GBLKS];
__device__ float g_partS1[Cc*GBLKS];
__device__ float g_partQ1[Cc*GBLKS];
__device__ float g_aff0[2*Cc];            // [a..., b...] affine for relu(bn)
__device__ float g_aff1[2*Cc];

// ---------------- f32x2 packed helpers (sm_100+) ----------------
__device__ __forceinline__ ull f2add(ull a, ull b){
    ull r; asm("add.rn.f32x2 %0,%1,%2;" : "=l"(r) : "l"(a), "l"(b)); return r;
}
__device__ __forceinline__ ull f2mul(ull a, ull b){
    ull r; asm("mul.rn.f32x2 %0,%1,%2;" : "=l"(r) : "l"(a), "l"(b)); return r;
}
__device__ __forceinline__ ull f2fma(ull a, ull b, ull c){
    ull r; asm("fma.rn.f32x2 %0,%1,%2,%3;" : "=l"(r) : "l"(a), "l"(b), "l"(c)); return r;
}
__device__ __forceinline__ ull fpack(float lo, float hi){
    ull r; asm("mov.b64 %0,{%1,%2};" : "=l"(r) : "f"(lo), "f"(hi)); return r;
}
__device__ __forceinline__ float2 funpack(ull p){
    float2 f; asm("mov.b64 {%0,%1},%2;" : "=f"(f.x), "=f"(f.y) : "l"(p)); return f;
}
__device__ __forceinline__ ull fdup_bits(float v){
    unsigned ub = __float_as_uint(v);
    return ((ull)ub << 32) | ub;
}

// ============================================================================
// 1) Farthest point sampling. One CTA per batch. 512 thr x 16 pts/thread.
//    Exact FP op-order of reference: d = (dx*dx+dy*dy)+dz*dz (f32x2 packed,
//    per-lane rounding identical); min_d=min(min_d,d); argmax earliest-index.
// ============================================================================
#define FPS_SMEM (3*Nc*4 + 2*16*8)

__global__ __launch_bounds__(512,1) void fps_kernel(const float* __restrict__ xyz,
                                                    float* __restrict__ out)
{
    const int b = blockIdx.x;
    extern __shared__ float smem_f[];
    float* X = smem_f;
    float* Y = smem_f + Nc;
    float* Z = smem_f + 2*Nc;
    ull* part = (ull*)(smem_f + 3*Nc);

    const float* base = xyz + (size_t)b*Nc*3;
    float* oxyz = out + (size_t)b*Sc*3;
    const int t = threadIdx.x;
    const int lane = t & 31, wid = t >> 5;

    ull px2[8], py2[8], pz2[8];
    float md[16];
#pragma unroll
    for (int jj = 0; jj < 8; jj++) {
        int p = t*16 + jj*2;
        float x0 = base[p*3+0], y0 = base[p*3+1], z0 = base[p*3+2];
        float x1 = base[p*3+3], y1 = base[p*3+4], z1 = base[p*3+5];
        px2[jj] = fpack(x0,x1); py2[jj] = fpack(y0,y1); pz2[jj] = fpack(z0,z1);
        md[2*jj] = 1e10f; md[2*jj+1] = 1e10f;
        X[p]=x0; Y[p]=y0; Z[p]=z0;
        X[p+1]=x1; Y[p+1]=y1; Z[p+1]=z1;
    }
    __syncthreads();

    float cx = X[0], cy = Y[0], cz = Z[0];

    for (int s = 0; s < Sc; s++) {
        if (t == 0) {
            oxyz[s*3+0]=cx; oxyz[s*3+1]=cy; oxyz[s*3+2]=cz;
        }
        if (s == Sc-1) break;

        // x - c == x + (-c) exactly in IEEE754
        ull ncx = fdup_bits(-cx), ncy = fdup_bits(-cy), ncz = fdup_bits(-cz);

        float best = -1.0f; int bidx = 0;
#pragma unroll
        for (int jj = 0; jj < 8; jj++) {
            ull dx = f2add(px2[jj], ncx);
            ull dy = f2add(py2[jj], ncy);
            ull dz = f2add(pz2[jj], ncz);
            ull d2 = f2add(f2add(f2mul(dx,dx), f2mul(dy,dy)), f2mul(dz,dz));
            float2 d = funpack(d2);
            float m0 = fminf(md[2*jj],   d.x); md[2*jj]   = m0;
            float m1 = fminf(md[2*jj+1], d.y); md[2*jj+1] = m1;
            if (m0 > best) { best = m0; bidx = t*16 + 2*jj; }
            if (m1 > best) { best = m1; bidx = t*16 + 2*jj + 1; }
        }

        // warp argmax: fmax butterfly + ballot (lane order == global idx order)
        float wm = best;
#pragma unroll
        for (int o = 16; o; o >>= 1)
            wm = fmaxf(wm, __shfl_xor_sync(FULLM, wm, o));
        unsigned bal = __ballot_sync(FULLM, best == wm);
        int src = __ffs(bal) - 1;
        int widx = __shfl_sync(FULLM, bidx, src);

        ull key = ((ull)__float_as_uint(wm) << 32) | (unsigned)(~widx);
        ull* pb = part + (s & 1)*16;   // double buffer, 1 bar/iter
        if (lane == 0) pb[wid] = key;
        __syncthreads();
        key = pb[lane & 15];
#pragma unroll
        for (int o = 8; o; o >>= 1) {
            ull ok = __shfl_xor_sync(FULLM, key, o);
            if (ok > key) key = ok;
        }
        int w = (int)(~(unsigned)key);
        cx = X[w]; cy = Y[w]; cz = Z[w];
    }
}

// ============================================================================
// 2) Brute-force KNN (K=16). 64 queries per CTA, 4 threads per query, each
//    scans a 2048-point chunk; exact lex-ordered merge of 4 stable top-16s.
//    d2 = (|q|^2 + |p|^2) - 2*q.p   (exact ref op order; d2 is never -0)
// ============================================================================
#define KNN_SMEM (Nc*16 + 64*64*8)

__device__ __forceinline__ unsigned okey(float f){
    unsigned u = __float_as_uint(f);
    return ((int)u < 0) ? ~u : (u | 0x80000000u);   // monotone order-preserving
}

__global__ __launch_bounds__(256,1) void knn_kernel(const float* __restrict__ xyz,
                                                    const float* __restrict__ newxyz)
{
    extern __shared__ float smem_f[];
    float4* tile = (float4*)smem_f;
    ull* merge = (ull*)(smem_f + Nc*4);
    const int blk = blockIdx.x;      // 128 blocks = 4 batches * 32
    const int b = blk >> 5;
    const int qbase = (blk & 31) * 64;
    const float* base = xyz + (size_t)b*Nc*3;

    for (int p = threadIdx.x; p < Nc; p += 256) {
        float x = base[p*3], y = base[p*3+1], z = base[p*3+2];
        float sq = __fadd_rn(__fadd_rn(__fmul_rn(x,x), __fmul_rn(y,y)), __fmul_rn(z,z));
        tile[p] = make_float4(x, y, z, sq);
    }
    __syncthreads();

    const int q = threadIdx.x & 63;
    const int ch = threadIdx.x >> 6;             // chunk 0..3
    const int qi = b*Sc + qbase + q;
    float qx = newxyz[qi*3], qy = newxyz[qi*3+1], qz = newxyz[qi*3+2];
    float sqq = __fadd_rn(__fadd_rn(__fmul_rn(qx,qx), __fmul_rn(qy,qy)), __fmul_rn(qz,qz));

    float dist[Kc]; int ids[Kc];
#pragma unroll
    for (int i = 0; i < Kc; i++) { dist[i] = 3.4e38f; ids[i] = 0; }
    float kth = 3.4e38f;

    const int p0 = ch*2048;
    for (int p = p0; p < p0 + 2048; p++) {
        float4 v = tile[p];
        float dot = __fadd_rn(__fadd_rn(__fmul_rn(qx,v.x), __fmul_rn(qy,v.y)),
                              __fmul_rn(qz,v.z));
        float d2 = __fsub_rn(__fadd_rn(sqq, v.w), __fadd_rn(dot, dot));
        if (d2 < kth) {
            int j = Kc-1;
            while (j > 0 && dist[j-1] > d2) {   // stable insertion
                dist[j] = dist[j-1]; ids[j] = ids[j-1]; j--;
            }
            dist[j] = d2; ids[j] = p;
            kth = dist[Kc-1];
        }
    }
    // store lex-sorted packed list
    ull* mylist = merge + q*64 + ch*16;
#pragma unroll
    for (int i = 0; i < Kc; i++)
        mylist[i] = ((ull)okey(dist[i]) << 32) | (unsigned)ids[i];
    __syncthreads();

    if (threadIdx.x < 64) {
        int mq = threadIdx.x;
        const ull* L = merge + mq*64;
        int h0 = 0, h1 = 16, h2 = 32, h3 = 48;
        int oq = (b*Sc + qbase + mq)*Kc;
#pragma unroll
        for (int r = 0; r < Kc; r++) {
            ull k0 = L[h0], k1 = L[h1], k2 = L[h2], k3 = L[h3];
            ull ka = (k0 <= k1) ? k0 : k1;
            ull kb = (k2 <= k3) ? k2 : k3;
            ull kw = (ka <= kb) ? ka : kb;
            g_knn[oq + r] = (int)(unsigned)kw;
            if (kw == k0) h0++; else if (kw == k1) h1++;
            else if (kw == k2) h2++; else h3++;
        }
    }
}

// ============================================================================
// 3) Gather + layer0 GEMM (M=131072, N=128, K=67) + BN-stat partials.
//    128x128 tile, 256 threads, 8x8 microtiles, packed f32x2 FFMA.
//    A stored duplicated (v,v) in smem so no per-k register dup.
// ============================================================================
#define G0_SMEM (68*128*8 + 68*128*4)

__global__ __launch_bounds__(256,2) void gemm0_kernel(const float* __restrict__ xyz,
                                                      const float* __restrict__ feat,
                                                      const float* __restrict__ w0,
                                                      const float* __restrict__ b0,
                                                      const float* __restrict__ newxyz)
{
    extern __shared__ float smem_f[];
    ull*   AD = (ull*)smem_f;                      // [68][128] dup-packed
    float* WS = smem_f + 68*128*2;                 // [68][128]
    const int t = threadIdx.x;
    const int blk = blockIdx.x;

    for (int i = t; i < Cc*67; i += 256) {         // w0: [C][67]
        int c = i / 67, f = i - c*67;
        WS[f*128 + c] = w0[i];
    }
    {
        int m = t & 127, half = t >> 7;
        int R = blk*128 + m;
        int bs = R >> 4;
        int b = bs >> 11;
        int nid = g_knn[R];
        const float* frow = feat + ((size_t)b*Nc + nid)*Fc;
        if (half == 0) {
            const float* prow = xyz + ((size_t)b*Nc + nid)*3;
            AD[0*128+m] = fdup_bits(__fsub_rn(prow[0], newxyz[bs*3+0]));
            AD[1*128+m] = fdup_bits(__fsub_rn(prow[1], newxyz[bs*3+1]));
            AD[2*128+m] = fdup_bits(__fsub_rn(prow[2], newxyz[bs*3+2]));
            for (int f = 0; f < 32; f += 4) {
                float4 v = *(const float4*)(frow + f);
                AD[(3+f)*128+m]=fdup_bits(v.x); AD[(4+f)*128+m]=fdup_bits(v.y);
                AD[(5+f)*128+m]=fdup_bits(v.z); AD[(6+f)*128+m]=fdup_bits(v.w);
            }
        } else {
            for (int f = 32; f < 64; f += 4) {
                float4 v = *(const float4*)(frow + f);
                AD[(3+f)*128+m]=fdup_bits(v.x); AD[(4+f)*128+m]=fdup_bits(v.y);
                AD[(5+f)*128+m]=fdup_bits(v.z); AD[(6+f)*128+m]=fdup_bits(v.w);
            }
        }
    }
    __syncthreads();

    const int tn = t & 15, tm = t >> 4;
    ull accp[8][4];
#pragma unroll
    for (int i = 0; i < 8; i++)
#pragma unroll
        for (int j = 0; j < 4; j++) accp[i][j] = 0;

    for (int kk = 0; kk < 67; kk++) {
        ulonglong2 a01 = *(const ulonglong2*)(AD + kk*128 + tm*8);
        ulonglong2 a23 = *(const ulonglong2*)(AD + kk*128 + tm*8 + 2);
        ulonglong2 a45 = *(const ulonglong2*)(AD + kk*128 + tm*8 + 4);
        ulonglong2 a67 = *(const ulonglong2*)(AD + kk*128 + tm*8 + 6);
        ulonglong2 wA  = *(const ulonglong2*)(WS + kk*128 + tn*8);
        ulonglong2 wB  = *(const ulonglong2*)(WS + kk*128 + tn*8 + 4);
        ull a[8] = {a01.x,a01.y,a23.x,a23.y,a45.x,a45.y,a67.x,a67.y};
        ull w[4] = {wA.x, wA.y, wB.x, wB.y};
#pragma unroll
        for (int i = 0; i < 8; i++)
#pragma unroll
            for (int j = 0; j < 4; j++) accp[i][j] = f2fma(a[i], w[j], accp[i][j]);
    }

    float bb[8], sum[8], ssq[8];
#pragma unroll
    for (int j = 0; j < 8; j++) { bb[j] = b0[tn*8+j]; sum[j]=0.f; ssq[j]=0.f; }
#pragma unroll
    for (int i = 0; i < 8; i++) {
        size_t row = (size_t)blk*128 + tm*8 + i;
        float v[8];
#pragma unroll
        for (int j = 0; j < 4; j++) {
            float2 u = funpack(accp[i][j]);
            v[2*j]   = __fadd_rn(u.x, bb[2*j]);
            v[2*j+1] = __fadd_rn(u.y, bb[2*j+1]);
        }
#pragma unroll
        for (int j = 0; j < 8; j++) {
            sum[j] += v[j];
            ssq[j] = fmaf(v[j], v[j], ssq[j]);
        }
        *(float4*)&g_h0[row*Cc + tn*8]     = make_float4(v[0],v[1],v[2],v[3]);
        *(float4*)&g_h0[row*Cc + tn*8 + 4] = make_float4(v[4],v[5],v[6],v[7]);
    }
    __syncthreads();
    float* st = smem_f;                     // reuse: [128ch][16tm] sum, +2048 ssq
#pragma unroll
    for (int j = 0; j < 8; j++) {
        st[(tn*8+j)*16 + tm]        = sum[j];
        st[2048 + (tn*8+j)*16 + tm] = ssq[j];
    }
    __syncthreads();
    if (t < Cc) {
        float s = 0.f, q = 0.f;
        for (int r = 0; r < 16; r++) { s += st[t*16+r]; q += st[2048 + t*16 + r]; }
        g_partS0[t*GBLKS + blk] = s;
        g_partQ0[t*GBLKS + blk] = q;
    }
}

// ============================================================================
// 4) BN stat reduce -> affine. 128 blocks (one per channel) x 256 threads,
//    coalesced reads, deterministic fp64 accumulation.
// ============================================================================
__global__ __launch_bounds__(256) void stats_kernel(int layer,
                                                    const float* __restrict__ gamma,
                                                    const float* __restrict__ beta)
{
    const float* PS = layer ? g_partS1 : g_partS0;
    const float* PQ = layer ? g_partQ1 : g_partQ0;
    float* aff = layer ? g_aff1 : g_aff0;
    const int c = blockIdx.x;
    const int t = threadIdx.x;
    double s = 0.0, q = 0.0;
    for (int i = t; i < GBLKS; i += 256) {
        s += (double)PS[c*GBLKS + i];
        q += (double)PQ[c*GBLKS + i];
    }
#pragma unroll
    for (int o = 16; o; o >>= 1) {
        s += __shfl_xor_sync(FULLM, s, o);
        q += __shfl_xor_sync(FULLM, q, o);
    }
    __shared__ double sw[16];
    int lane = t & 31, wid = t >> 5;
    if (lane == 0) { sw[wid*2] = s; sw[wid*2+1] = q; }
    __syncthreads();
    if (t == 0) {
        double S = 0.0, Q = 0.0;
        for (int w = 0; w < 8; w++) { S += sw[w*2]; Q += sw[w*2+1]; }
        double cnt = (double)MTOT;
        double mean = S / cnt;
        double var = Q / cnt - mean*mean;
        float a = gamma[c] * (float)(1.0 / sqrt(var + 1e-5));
        aff[c] = a;
        aff[Cc + c] = __fsub_rn(beta[c], (float)mean * a);
    }
}

// ============================================================================
// 5) Layer1 GEMM (K=128): A = relu(affine0(h0)) dup-packed, W = w1. + BN1.
// ============================================================================
#define G1_SMEM (128*128*8 + 128*128*4)

__global__ __launch_bounds__(256,1) void gemm1_kernel(const float* __restrict__ w1,
                                                      const float* __restrict__ b1)
{
    extern __shared__ float smem_f[];
    ull*   AD = (ull*)smem_f;                      // [128][128] dup-packed
    float* WS = smem_f + 128*128*2;                // [128][128]
    const int t = threadIdx.x;
    const int blk = blockIdx.x;

    for (int i = t; i < Cc*Cc; i += 256) {         // w1: [C][C]
        int c = i >> 7, f = i & 127;
        WS[f*128 + c] = w1[i];
    }
    {
        int m = t & 127, half = t >> 7;
        size_t R = (size_t)blk*128 + m;
        const float* hrow = g_h0 + R*Cc + half*64;
        for (int f = 0; f < 64; f += 4) {
            float4 v = *(const float4*)(hrow + f);
            int fg = half*64 + f;
            AD[(fg+0)*128+m] = fdup_bits(fmaxf(fmaf(g_aff0[fg+0], v.x, g_aff0[Cc+fg+0]), 0.f));
            AD[(fg+1)*128+m] = fdup_bits(fmaxf(fmaf(g_aff0[fg+1], v.y, g_aff0[Cc+fg+1]), 0.f));
            AD[(fg+2)*128+m] = fdup_bits(fmaxf(fmaf(g_aff0[fg+2], v.z, g_aff0[Cc+fg+2]), 0.f));
            AD[(fg+3)*128+m] = fdup_bits(fmaxf(fmaf(g_aff0[fg+3], v.w, g_aff0[Cc+fg+3]), 0.f));
        }
    }
    __syncthreads();

    const int tn = t & 15, tm = t >> 4;
    ull accp[8][4];
#pragma unroll
    for (int i = 0; i < 8; i++)
#pragma unroll
        for (int j = 0; j < 4; j++) accp[i][j] = 0;

    for (int kk = 0; kk < Cc; kk++) {
        ulonglong2 a01 = *(const ulonglong2*)(AD + kk*128 + tm*8);
        ulonglong2 a23 = *(const ulonglong2*)(AD + kk*128 + tm*8 + 2);
        ulonglong2 a45 = *(const ulonglong2*)(AD + kk*128 + tm*8 + 4);
        ulonglong2 a67 = *(const ulonglong2*)(AD + kk*128 + tm*8 + 6);
        ulonglong2 wA  = *(const ulonglong2*)(WS + kk*128 + tn*8);
        ulonglong2 wB  = *(const ulonglong2*)(WS + kk*128 + tn*8 + 4);
        ull a[8] = {a01.x,a01.y,a23.x,a23.y,a45.x,a45.y,a67.x,a67.y};
        ull w[4] = {wA.x, wA.y, wB.x, wB.y};
#pragma unroll
        for (int i = 0; i < 8; i++)
#pragma unroll
            for (int j = 0; j < 4; j++) accp[i][j] = f2fma(a[i], w[j], accp[i][j]);
    }

    float bb[8], sum[8], ssq[8];
#pragma unroll
    for (int j = 0; j < 8; j++) { bb[j] = b1[tn*8+j]; sum[j]=0.f; ssq[j]=0.f; }
#pragma unroll
    for (int i = 0; i < 8; i++) {
        size_t row = (size_t)blk*128 + tm*8 + i;
        float v[8];
#pragma unroll
        for (int j = 0; j < 4; j++) {
            float2 u = funpack(accp[i][j]);
            v[2*j]   = __fadd_rn(u.x, bb[2*j]);
            v[2*j+1] = __fadd_rn(u.y, bb[2*j+1]);
        }
#pragma unroll
        for (int j = 0; j < 8; j++) {
            sum[j] += v[j];
            ssq[j] = fmaf(v[j], v[j], ssq[j]);
        }
        *(float4*)&g_h1[row*Cc + tn*8]     = make_float4(v[0],v[1],v[2],v[3]);
        *(float4*)&g_h1[row*Cc + tn*8 + 4] = make_float4(v[4],v[5],v[6],v[7]);
    }
    __syncthreads();
    float* st = smem_f;
#pragma unroll
    for (int j = 0; j < 8; j++) {
        st[(tn*8+j)*16 + tm]        = sum[j];
        st[2048 + (tn*8+j)*16 + tm] = ssq[j];
    }
    __syncthreads();
    if (t < Cc) {
        float s = 0.f, q = 0.f;
        for (int r = 0; r < 16; r++) { s += st[t*16+r]; q += st[2048 + t*16 + r]; }
        g_partS1[t*GBLKS + blk] = s;
        g_partQ1[t*GBLKS + blk] = q;
    }
}

// ============================================================================
// 6) relu(affine1(h1)) then max over K -> new_features
// ============================================================================
__global__ __launch_bounds__(256) void final_kernel(float* __restrict__ out)
{
    int gid = blockIdx.x*256 + threadIdx.x;     // B*S*C = 1,048,576
    int c = gid & 127, bs = gid >> 7;
    float a = g_aff1[c], b = g_aff1[Cc + c];
    float m = -3.4e38f;
#pragma unroll
    for (int k = 0; k < Kc; k++) {
        float h = g_h1[((size_t)(bs*Kc + k))*Cc + c];
        float v = fmaxf(fmaf(a, h, b), 0.f);
        m = fmaxf(m, v);
    }
    out[Bc*Sc*3 + gid] = m;
}

// ============================================================================
extern "C" void kernel_launch(void* const* d_in, const int* in_sizes, int n_in,
                              void* d_out, int out_size)
{
    const float* xyz  = (const float*)d_in[0];
    const float* feat = (const float*)d_in[1];
    const float* w0   = (const float*)d_in[2];
    const float* b0   = (const float*)d_in[3];
    const float* g0   = (const float*)d_in[4];
    const float* be0  = (const float*)d_in[5];
    const float* w1   = (const float*)d_in[6];
    const float* b1   = (const float*)d_in[7];
    const float* g1   = (const float*)d_in[8];
    const float* be1  = (const float*)d_in[9];
    float* out = (float*)d_out;

    cudaFuncSetAttribute(fps_kernel,   cudaFuncAttributeMaxDynamicSharedMemorySize, FPS_SMEM);
    cudaFuncSetAttribute(knn_kernel,   cudaFuncAttributeMaxDynamicSharedMemorySize, KNN_SMEM);
    cudaFuncSetAttribute(gemm0_kernel, cudaFuncAttributeMaxDynamicSharedMemorySize, G0_SMEM);
    cudaFuncSetAttribute(gemm1_kernel, cudaFuncAttributeMaxDynamicSharedMemorySize, G1_SMEM);

    fps_kernel  <<<Bc, 512, FPS_SMEM>>>(xyz, out);
    knn_kernel  <<<128, 256, KNN_SMEM>>>(xyz, out);
    gemm0_kernel<<<GBLKS, 256, G0_SMEM>>>(xyz, feat, w0, b0, out);
    stats_kernel<<<Cc, 256>>>(0, g0, be0);
    gemm1_kernel<<<GBLKS, 256, G1_SMEM>>>(w1, b1);
    stats_kernel<<<Cc, 256>>>(1, g1, be1);
    final_kernel<<<(Bc*Sc*Cc)/256, 256>>>(out);
}

// round 4
// speedup vs baseline: 1.2281x; 1.0970x over previous
#include <cuda_runtime.h>
#include <cstdint>

// Problem constants
#define Bc 4
#define Nc 8192
#define Fc 64
#define Sc 2048
#define Kc 16
#define Cc 128
#define MTOT (Bc*Sc*Kc)          // 131072 rows through the MLP
#define GBLKS (MTOT/128)         // 1024 gemm blocks
#define FULLM 0xffffffffu

typedef unsigned long long ull;

// -------- scratch (static device allocations; no cudaMalloc allowed) --------
__device__ float g_h0[(size_t)MTOT*Cc];   // 64 MB, pre-BN layer0 output
__device__ float g_h1[(size_t)MTOT*Cc];   // 64 MB, pre-BN layer1 output
__device__ int   g_knn[Bc*Sc*Kc];
__device__ float g_partS0[Cc*GBLKS];      // [c][blk] coalesced for stats
__device__ float g_partQ0[Cc*GBLKS];
__device__ float g_partS1[Cc*GBLKS];
__device__ float g_partQ1[Cc*GBLKS];
__device__ float g_aff0[2*Cc];            // [a..., b...] affine for relu(bn)
__device__ float g_aff1[2*Cc];

// ---------------- f32x2 packed helpers (sm_100+) ----------------
__device__ __forceinline__ ull f2add(ull a, ull b){
    ull r; asm("add.rn.f32x2 %0,%1,%2;" : "=l"(r) : "l"(a), "l"(b)); return r;
}
__device__ __forceinline__ ull f2mul(ull a, ull b){
    ull r; asm("mul.rn.f32x2 %0,%1,%2;" : "=l"(r) : "l"(a), "l"(b)); return r;
}
__device__ __forceinline__ ull f2fma(ull a, ull b, ull c){
    ull r; asm("fma.rn.f32x2 %0,%1,%2,%3;" : "=l"(r) : "l"(a), "l"(b), "l"(c)); return r;
}
__device__ __forceinline__ ull fpack(float lo, float hi){
    ull r; asm("mov.b64 %0,{%1,%2};" : "=l"(r) : "f"(lo), "f"(hi)); return r;
}
__device__ __forceinline__ float2 funpack(ull p){
    float2 f; asm("mov.b64 {%0,%1},%2;" : "=f"(f.x), "=f"(f.y) : "l"(p)); return f;
}
__device__ __forceinline__ ull fdup_bits(float v){
    unsigned ub = __float_as_uint(v);
    return ((ull)ub << 32) | ub;
}

// ---------------- cluster / mbarrier helpers ----------------
__device__ __forceinline__ uint32_t smem_u32(const void* p){
    uint32_t a;
    asm("{ .reg .u64 t; cvta.to.shared.u64 t, %1; cvt.u32.u64 %0, t; }"
        : "=r"(a) : "l"(p));
    return a;
}
__device__ __forceinline__ uint32_t ctarank(){
    uint32_t r; asm("mov.u32 %0, %%cluster_ctarank;" : "=r"(r)); return r;
}
__device__ __forceinline__ void mbar_init(uint32_t addr, uint32_t cnt){
    asm volatile("mbarrier.init.shared.b64 [%0], %1;" :: "r"(addr), "r"(cnt) : "memory");
}
__device__ __forceinline__ void cluster_sync(){
    asm volatile("barrier.cluster.arrive.aligned;" ::: "memory");
    asm volatile("barrier.cluster.wait.aligned;" ::: "memory");
}
// store CTA key into peer's slot, then arrive on peer's mbarrier (release.cluster)
__device__ __forceinline__ void publish_key(uint32_t slot_addr, uint32_t mbar_addr,
                                            uint32_t peer, ull key){
    uint32_t rs, rb;
    asm volatile("mapa.shared::cluster.u32 %0, %1, %2;" : "=r"(rs) : "r"(slot_addr), "r"(peer));
    asm volatile("st.shared::cluster.u64 [%0], %1;" :: "r"(rs), "l"(key) : "memory");
    asm volatile("mapa.shared::cluster.u32 %0, %1, %2;" : "=r"(rb) : "r"(mbar_addr), "r"(peer));
    asm volatile("mbarrier.arrive.shared::cluster.b64 _, [%0];" :: "r"(rb) : "memory");
}
__device__ __forceinline__ void mbar_wait_acq_cluster(uint32_t addr, int phase){
    asm volatile(
        "{\n\t.reg .pred P;\n\t"
        "WL_%=:\n\t"
        "mbarrier.try_wait.parity.acquire.cluster.shared::cta.b64 P, [%0], %1, 0x989680;\n\t"
        "@!P bra WL_%=;\n\t"
        "}" :: "r"(addr), "r"(phase) : "memory");
}
__device__ __forceinline__ unsigned redux_max_u32(unsigned v){
    unsigned r, m = FULLM;
    asm volatile("redux.sync.max.u32 %0, %1, %2;" : "=r"(r) : "r"(v), "r"(m));
    return r;
}

// ============================================================================
// 1) Farthest point sampling, 4-CTA cluster per batch. Each CTA owns 2048
//    points (4/thread, f32x2 packed), keeps full xyz copy for winner lookup.
//    Per iter: warp redux argmax -> CTA reduce -> DSMEM key exchange with
//    double-buffered mbarriers -> global winner. Bit-exact vs reference:
//    d=((dx*dx+dy*dy)+dz*dz), min_d=min(min_d,d), argmax first-index ties.
// ============================================================================
#define FPS_CLUS 4
#define FPS_OFF_PART  (3*Nc*4)                 // ull[16]
#define FPS_OFF_SLOT  (FPS_OFF_PART + 16*8)    // ull[2][4]
#define FPS_OFF_MBAR  (FPS_OFF_SLOT + 2*4*8)   // u64[2]
#define FPS_SMEM      (FPS_OFF_MBAR + 2*8 + 16)

__global__ __launch_bounds__(512,1) __cluster_dims__(FPS_CLUS,1,1)
void fps_kernel(const float* __restrict__ xyz, float* __restrict__ out)
{
    extern __shared__ float smem_f[];
    float* X = smem_f;
    float* Y = smem_f + Nc;
    float* Z = smem_f + 2*Nc;
    const uint32_t sbase = smem_u32(smem_f);
    ull* part = (ull*)((char*)smem_f + FPS_OFF_PART);
    ull* slot = (ull*)((char*)smem_f + FPS_OFF_SLOT);   // [2][4]
    const uint32_t slot_a = sbase + FPS_OFF_SLOT;
    const uint32_t mbar_a = sbase + FPS_OFF_MBAR;

    const int t = threadIdx.x;
    const int lane = t & 31, wid = t >> 5;
    const uint32_t rank = ctarank();
    const int b = blockIdx.x / FPS_CLUS;

    const float* base = xyz + (size_t)b*Nc*3;
    float* oxyz = out + (size_t)b*Sc*3;

    // full cloud copy for winner lookup
    for (int p = t; p < Nc; p += 512) {
        X[p] = base[p*3+0]; Y[p] = base[p*3+1]; Z[p] = base[p*3+2];
    }
    if (t == 0) { mbar_init(mbar_a, FPS_CLUS); mbar_init(mbar_a + 8, FPS_CLUS); }
    __syncthreads();
    cluster_sync();           // mbarriers + smem visible cluster-wide

    // this CTA's 4 points/thread, packed
    const int pbase = (int)rank*2048 + t*4;
    ull px2[2], py2[2], pz2[2];
    float md[4];
#pragma unroll
    for (int jj = 0; jj < 2; jj++) {
        int p = pbase + jj*2;
        px2[jj] = fpack(X[p], X[p+1]);
        py2[jj] = fpack(Y[p], Y[p+1]);
        pz2[jj] = fpack(Z[p], Z[p+1]);
        md[2*jj] = 1e10f; md[2*jj+1] = 1e10f;
    }

    float cx = X[0], cy = Y[0], cz = Z[0];
    int ph0 = 0, ph1 = 0;

    for (int s = 0; s < Sc; s++) {
        if (rank == 0 && t == 0) {
            oxyz[s*3+0]=cx; oxyz[s*3+1]=cy; oxyz[s*3+2]=cz;
        }
        if (s == Sc-1) break;

        // x - c == x + (-c) exactly in IEEE754
        ull ncx = fdup_bits(-cx), ncy = fdup_bits(-cy), ncz = fdup_bits(-cz);

        float best = -1.0f; int bidx = 0;
#pragma unroll
        for (int jj = 0; jj < 2; jj++) {
            ull dx = f2add(px2[jj], ncx);
            ull dy = f2add(py2[jj], ncy);
            ull dz = f2add(pz2[jj], ncz);
            ull d2 = f2add(f2add(f2mul(dx,dx), f2mul(dy,dy)), f2mul(dz,dz));
            float2 d = funpack(d2);
            float m0 = fminf(md[2*jj],   d.x); md[2*jj]   = m0;
            float m1 = fminf(md[2*jj+1], d.y); md[2*jj+1] = m1;
            if (m0 > best) { best = m0; bidx = pbase + 2*jj; }
            if (m1 > best) { best = m1; bidx = pbase + 2*jj + 1; }
        }

        // warp argmax: values are >= +0 so float bits are order-monotone
        unsigned ub = __float_as_uint(best);
        unsigned wb = redux_max_u32(ub);
        unsigned bal = __ballot_sync(FULLM, ub == wb);
        int src = __ffs(bal) - 1;                 // lane order == index order
        int widx = __shfl_sync(FULLM, bidx, src);
        ull wkey = ((ull)wb << 32) | (unsigned)(~widx);
        if (lane == 0) part[wid] = wkey;
        __syncthreads();

        const int ib = s & 1;
        if (wid == 0) {
            ull key = part[lane & 15];
#pragma unroll
            for (int o = 8; o; o >>= 1) {
                ull ok = __shfl_xor_sync(FULLM, key, o);
                if (ok > key) key = ok;
            }
            if (lane < FPS_CLUS)   // lane i -> peer CTA i, slot[ib][myrank]
                publish_key(slot_a + (ib*4 + rank)*8, mbar_a + ib*8,
                            (uint32_t)lane, key);
        }

        int phase = ib ? ph1 : ph0;
        mbar_wait_acq_cluster(mbar_a + ib*8, phase);
        if (ib) ph1 ^= 1; else ph0 ^= 1;

        ull k0 = slot[ib*4+0], k1 = slot[ib*4+1];
        ull k2 = slot[ib*4+2], k3 = slot[ib*4+3];
        ull ka = (k0 > k1) ? k0 : k1;
        ull kb = (k2 > k3) ? k2 : k3;
        ull kw = (ka > kb) ? ka : kb;
        int w = (int)(~(unsigned)kw);
        cx = X[w]; cy = Y[w]; cz = Z[w];
    }
    cluster_sync();
}

// ============================================================================
// 2) Brute-force KNN (K=16). 64 queries per CTA, 4 threads per query, each
//    scans a 2048-point chunk; exact lex-ordered merge of 4 stable top-16s.
//    d2 = (|q|^2 + |p|^2) - 2*q.p   (exact ref op order; d2 is never -0)
// ============================================================================
#define KNN_SMEM (Nc*16 + 64*64*8)

__device__ __forceinline__ unsigned okey(float f){
    unsigned u = __float_as_uint(f);
    return ((int)u < 0) ? ~u : (u | 0x80000000u);   // monotone order-preserving
}

__global__ __launch_bounds__(256,1) void knn_kernel(const float* __restrict__ xyz,
                                                    const float* __restrict__ newxyz)
{
    extern __shared__ float smem_f[];
    float4* tile = (float4*)smem_f;
    ull* merge = (ull*)(smem_f + Nc*4);
    const int blk = blockIdx.x;      // 128 blocks = 4 batches * 32
    const int b = blk >> 5;
    const int qbase = (blk & 31) * 64;
    const float* base = xyz + (size_t)b*Nc*3;

    for (int p = threadIdx.x; p < Nc; p += 256) {
        float x = base[p*3], y = base[p*3+1], z = base[p*3+2];
        float sq = __fadd_rn(__fadd_rn(__fmul_rn(x,x), __fmul_rn(y,y)), __fmul_rn(z,z));
        tile[p] = make_float4(x, y, z, sq);
    }
    __syncthreads();

    const int q = threadIdx.x & 63;
    const int ch = threadIdx.x >> 6;             // chunk 0..3
    const int qi = b*Sc + qbase + q;
    float qx = newxyz[qi*3], qy = newxyz[qi*3+1], qz = newxyz[qi*3+2];
    float sqq = __fadd_rn(__fadd_rn(__fmul_rn(qx,qx), __fmul_rn(qy,qy)), __fmul_rn(qz,qz));

    float dist[Kc]; int ids[Kc];
#pragma unroll
    for (int i = 0; i < Kc; i++) { dist[i] = 3.4e38f; ids[i] = 0; }
    float kth = 3.4e38f;

    const int p0 = ch*2048;
    for (int p = p0; p < p0 + 2048; p++) {
        float4 v = tile[p];
        float dot = __fadd_rn(__fadd_rn(__fmul_rn(qx,v.x), __fmul_rn(qy,v.y)),
                              __fmul_rn(qz,v.z));
        float d2 = __fsub_rn(__fadd_rn(sqq, v.w), __fadd_rn(dot, dot));
        if (d2 < kth) {
            int j = Kc-1;
            while (j > 0 && dist[j-1] > d2) {   // stable insertion
                dist[j] = dist[j-1]; ids[j] = ids[j-1]; j--;
            }
            dist[j] = d2; ids[j] = p;
            kth = dist[Kc-1];
        }
    }
    // store lex-sorted packed list
    ull* mylist = merge + q*64 + ch*16;
#pragma unroll
    for (int i = 0; i < Kc; i++)
        mylist[i] = ((ull)okey(dist[i]) << 32) | (unsigned)ids[i];
    __syncthreads();

    if (threadIdx.x < 64) {
        int mq = threadIdx.x;
        const ull* L = merge + mq*64;
        int h0 = 0, h1 = 16, h2 = 32, h3 = 48;
        int oq = (b*Sc + qbase + mq)*Kc;
#pragma unroll
        for (int r = 0; r < Kc; r++) {
            ull k0 = L[h0], k1 = L[h1], k2 = L[h2], k3 = L[h3];
            ull ka = (k0 <= k1) ? k0 : k1;
            ull kb = (k2 <= k3) ? k2 : k3;
            ull kw = (ka <= kb) ? ka : kb;
            g_knn[oq + r] = (int)(unsigned)kw;
            if (kw == k0) h0++; else if (kw == k1) h1++;
            else if (kw == k2) h2++; else h3++;
        }
    }
}

// ============================================================================
// 3) Gather + layer0 GEMM (M=131072, N=128, K=67) + BN-stat partials.
//    128x128 tile, 256 threads, 8x8 microtiles, packed f32x2 FFMA.
//    A stored duplicated (v,v) in smem so no per-k register dup.
// ============================================================================
#define G0_SMEM (68*128*8 + 68*128*4)

__global__ __launch_bounds__(256,2) void gemm0_kernel(const float* __restrict__ xyz,
                                                      const float* __restrict__ feat,
                                                      const float* __restrict__ w0,
                                                      const float* __restrict__ b0,
                                                      const float* __restrict__ newxyz)
{
    extern __shared__ float smem_f[];
    ull*   AD = (ull*)smem_f;                      // [68][128] dup-packed
    float* WS = smem_f + 68*128*2;                 // [68][128]
    const int t = threadIdx.x;
    const int blk = blockIdx.x;

    for (int i = t; i < Cc*67; i += 256) {         // w0: [C][67]
        int c = i / 67, f = i - c*67;
        WS[f*128 + c] = w0[i];
    }
    {
        int m = t & 127, half = t >> 7;
        int R = blk*128 + m;
        int bs = R >> 4;
        int b = bs >> 11;
        int nid = g_knn[R];
        const float* frow = feat + ((size_t)b*Nc + nid)*Fc;
        if (half == 0) {
            const float* prow = xyz + ((size_t)b*Nc + nid)*3;
            AD[0*128+m] = fdup_bits(__fsub_rn(prow[0], newxyz[bs*3+0]));
            AD[1*128+m] = fdup_bits(__fsub_rn(prow[1], newxyz[bs*3+1]));
            AD[2*128+m] = fdup_bits(__fsub_rn(prow[2], newxyz[bs*3+2]));
            for (int f = 0; f < 32; f += 4) {
                float4 v = *(const float4*)(frow + f);
                AD[(3+f)*128+m]=fdup_bits(v.x); AD[(4+f)*128+m]=fdup_bits(v.y);
                AD[(5+f)*128+m]=fdup_bits(v.z); AD[(6+f)*128+m]=fdup_bits(v.w);
            }
        } else {
            for (int f = 32; f < 64; f += 4) {
                float4 v = *(const float4*)(frow + f);
                AD[(3+f)*128+m]=fdup_bits(v.x); AD[(4+f)*128+m]=fdup_bits(v.y);
                AD[(5+f)*128+m]=fdup_bits(v.z); AD[(6+f)*128+m]=fdup_bits(v.w);
            }
        }
    }
    __syncthreads();

    const int tn = t & 15, tm = t >> 4;
    ull accp[8][4];
#pragma unroll
    for (int i = 0; i < 8; i++)
#pragma unroll
        for (int j = 0; j < 4; j++) accp[i][j] = 0;

    for (int kk = 0; kk < 67; kk++) {
        ulonglong2 a01 = *(const ulonglong2*)(AD + kk*128 + tm*8);
        ulonglong2 a23 = *(const ulonglong2*)(AD + kk*128 + tm*8 + 2);
        ulonglong2 a45 = *(const ulonglong2*)(AD + kk*128 + tm*8 + 4);
        ulonglong2 a67 = *(const ulonglong2*)(AD + kk*128 + tm*8 + 6);
        ulonglong2 wA  = *(const ulonglong2*)(WS + kk*128 + tn*8);
        ulonglong2 wB  = *(const ulonglong2*)(WS + kk*128 + tn*8 + 4);
        ull a[8] = {a01.x,a01.y,a23.x,a23.y,a45.x,a45.y,a67.x,a67.y};
        ull w[4] = {wA.x, wA.y, wB.x, wB.y};
#pragma unroll
        for (int i = 0; i < 8; i++)
#pragma unroll
            for (int j = 0; j < 4; j++) accp[i][j] = f2fma(a[i], w[j], accp[i][j]);
    }

    float bb[8], sum[8], ssq[8];
#pragma unroll
    for (int j = 0; j < 8; j++) { bb[j] = b0[tn*8+j]; sum[j]=0.f; ssq[j]=0.f; }
#pragma unroll
    for (int i = 0; i < 8; i++) {
        size_t row = (size_t)blk*128 + tm*8 + i;
        float v[8];
#pragma unroll
        for (int j = 0; j < 4; j++) {
            float2 u = funpack(accp[i][j]);
            v[2*j]   = __fadd_rn(u.x, bb[2*j]);
            v[2*j+1] = __fadd_rn(u.y, bb[2*j+1]);
        }
#pragma unroll
        for (int j = 0; j < 8; j++) {
            sum[j] += v[j];
            ssq[j] = fmaf(v[j], v[j], ssq[j]);
        }
        *(float4*)&g_h0[row*Cc + tn*8]     = make_float4(v[0],v[1],v[2],v[3]);
        *(float4*)&g_h0[row*Cc + tn*8 + 4] = make_float4(v[4],v[5],v[6],v[7]);
    }
    __syncthreads();
    float* st = smem_f;                     // reuse: [128ch][16tm] sum, +2048 ssq
#pragma unroll
    for (int j = 0; j < 8; j++) {
        st[(tn*8+j)*16 + tm]        = sum[j];
        st[2048 + (tn*8+j)*16 + tm] = ssq[j];
    }
    __syncthreads();
    if (t < Cc) {
        float s = 0.f, q = 0.f;
        for (int r = 0; r < 16; r++) { s += st[t*16+r]; q += st[2048 + t*16 + r]; }
        g_partS0[t*GBLKS + blk] = s;
        g_partQ0[t*GBLKS + blk] = q;
    }
}

// ============================================================================
// 4) BN stat reduce -> affine. 128 blocks (one per channel) x 256 threads,
//    coalesced reads, deterministic fp64 accumulation.
// ============================================================================
__global__ __launch_bounds__(256) void stats_kernel(int layer,
                                                    const float* __restrict__ gamma,
                                                    const float* __restrict__ beta)
{
    const float* PS = layer ? g_partS1 : g_partS0;
    const float* PQ = layer ? g_partQ1 : g_partQ0;
    float* aff = layer ? g_aff1 : g_aff0;
    const int c = blockIdx.x;
    const int t = threadIdx.x;
    double s = 0.0, q = 0.0;
    for (int i = t; i < GBLKS; i += 256) {
        s += (double)PS[c*GBLKS + i];
        q += (double)PQ[c*GBLKS + i];
    }
#pragma unroll
    for (int o = 16; o; o >>= 1) {
        s += __shfl_xor_sync(FULLM, s, o);
        q += __shfl_xor_sync(FULLM, q, o);
    }
    __shared__ double sw[16];
    int lane = t & 31, wid = t >> 5;
    if (lane == 0) { sw[wid*2] = s; sw[wid*2+1] = q; }
    __syncthreads();
    if (t == 0) {
        double S = 0.0, Q = 0.0;
        for (int w = 0; w < 8; w++) { S += sw[w*2]; Q += sw[w*2+1]; }
        double cnt = (double)MTOT;
        double mean = S / cnt;
        double var = Q / cnt - mean*mean;
        float a = gamma[c] * (float)(1.0 / sqrt(var + 1e-5));
        aff[c] = a;
        aff[Cc + c] = __fsub_rn(beta[c], (float)mean * a);
    }
}

// ============================================================================
// 5) Layer1 GEMM (K=128): A = relu(affine0(h0)) dup-packed, W = w1. + BN1.
// ============================================================================
#define G1_SMEM (128*128*8 + 128*128*4)

__global__ __launch_bounds__(256,1) void gemm1_kernel(const float* __restrict__ w1,
                                                      const float* __restrict__ b1)
{
    extern __shared__ float smem_f[];
    ull*   AD = (ull*)smem_f;                      // [128][128] dup-packed
    float* WS = smem_f + 128*128*2;                // [128][128]
    const int t = threadIdx.x;
    const int blk = blockIdx.x;

    for (int i = t; i < Cc*Cc; i += 256) {         // w1: [C][C]
        int c = i >> 7, f = i & 127;
        WS[f*128 + c] = w1[i];
    }
    {
        int m = t & 127, half = t >> 7;
        size_t R = (size_t)blk*128 + m;
        const float* hrow = g_h0 + R*Cc + half*64;
        for (int f = 0; f < 64; f += 4) {
            float4 v = *(const float4*)(hrow + f);
            int fg = half*64 + f;
            AD[(fg+0)*128+m] = fdup_bits(fmaxf(fmaf(g_aff0[fg+0], v.x, g_aff0[Cc+fg+0]), 0.f));
            AD[(fg+1)*128+m] = fdup_bits(fmaxf(fmaf(g_aff0[fg+1], v.y, g_aff0[Cc+fg+1]), 0.f));
            AD[(fg+2)*128+m] = fdup_bits(fmaxf(fmaf(g_aff0[fg+2], v.z, g_aff0[Cc+fg+2]), 0.f));
            AD[(fg+3)*128+m] = fdup_bits(fmaxf(fmaf(g_aff0[fg+3], v.w, g_aff0[Cc+fg+3]), 0.f));
        }
    }
    __syncthreads();

    const int tn = t & 15, tm = t >> 4;
    ull accp[8][4];
#pragma unroll
    for (int i = 0; i < 8; i++)
#pragma unroll
        for (int j = 0; j < 4; j++) accp[i][j] = 0;

    for (int kk = 0; kk < Cc; kk++) {
        ulonglong2 a01 = *(const ulonglong2*)(AD + kk*128 + tm*8);
        ulonglong2 a23 = *(const ulonglong2*)(AD + kk*128 + tm*8 + 2);
        ulonglong2 a45 = *(const ulonglong2*)(AD + kk*128 + tm*8 + 4);
        ulonglong2 a67 = *(const ulonglong2*)(AD + kk*128 + tm*8 + 6);
        ulonglong2 wA  = *(const ulonglong2*)(WS + kk*128 + tn*8);
        ulonglong2 wB  = *(const ulonglong2*)(WS + kk*128 + tn*8 + 4);
        ull a[8] = {a01.x,a01.y,a23.x,a23.y,a45.x,a45.y,a67.x,a67.y};
        ull w[4] = {wA.x, wA.y, wB.x, wB.y};
#pragma unroll
        for (int i = 0; i < 8; i++)
#pragma unroll
            for (int j = 0; j < 4; j++) accp[i][j] = f2fma(a[i], w[j], accp[i][j]);
    }

    float bb[8], sum[8], ssq[8];
#pragma unroll
    for (int j = 0; j < 8; j++) { bb[j] = b1[tn*8+j]; sum[j]=0.f; ssq[j]=0.f; }
#pragma unroll
    for (int i = 0; i < 8; i++) {
        size_t row = (size_t)blk*128 + tm*8 + i;
        float v[8];
#pragma unroll
        for (int j = 0; j < 4; j++) {
            float2 u = funpack(accp[i][j]);
            v[2*j]   = __fadd_rn(u.x, bb[2*j]);
            v[2*j+1] = __fadd_rn(u.y, bb[2*j+1]);
        }
#pragma unroll
        for (int j = 0; j < 8; j++) {
            sum[j] += v[j];
            ssq[j] = fmaf(v[j], v[j], ssq[j]);
        }
        *(float4*)&g_h1[row*Cc + tn*8]     = make_float4(v[0],v[1],v[2],v[3]);
        *(float4*)&g_h1[row*Cc + tn*8 + 4] = make_float4(v[4],v[5],v[6],v[7]);
    }
    __syncthreads();
    float* st = smem_f;
#pragma unroll
    for (int j = 0; j < 8; j++) {
        st[(tn*8+j)*16 + tm]        = sum[j];
        st[2048 + (tn*8+j)*16 + tm] = ssq[j];
    }
    __syncthreads();
    if (t < Cc) {
        float s = 0.f, q = 0.f;
        for (int r = 0; r < 16; r++) { s += st[t*16+r]; q += st[2048 + t*16 + r]; }
        g_partS1[t*GBLKS + blk] = s;
        g_partQ1[t*GBLKS + blk] = q;
    }
}

// ============================================================================
// 6) relu(affine1(h1)) then max over K -> new_features
// ============================================================================
__global__ __launch_bounds__(256) void final_kernel(float* __restrict__ out)
{
    int gid = blockIdx.x*256 + threadIdx.x;     // B*S*C = 1,048,576
    int c = gid & 127, bs = gid >> 7;
    float a = g_aff1[c], b = g_aff1[Cc + c];
    float m = -3.4e38f;
#pragma unroll
    for (int k = 0; k < Kc; k++) {
        float h = g_h1[((size_t)(bs*Kc + k))*Cc + c];
        float v = fmaxf(fmaf(a, h, b), 0.f);
        m = fmaxf(m, v);
    }
    out[Bc*Sc*3 + gid] = m;
}

// ============================================================================
extern "C" void kernel_launch(void* const* d_in, const int* in_sizes, int n_in,
                              void* d_out, int out_size)
{
    const float* xyz  = (const float*)d_in[0];
    const float* feat = (const float*)d_in[1];
    const float* w0   = (const float*)d_in[2];
    const float* b0   = (const float*)d_in[3];
    const float* g0   = (const float*)d_in[4];
    const float* be0  = (const float*)d_in[5];
    const float* w1   = (const float*)d_in[6];
    const float* b1   = (const float*)d_in[7];
    const float* g1   = (const float*)d_in[8];
    const float* be1  = (const float*)d_in[9];
    float* out = (float*)d_out;

    cudaFuncSetAttribute(fps_kernel,   cudaFuncAttributeMaxDynamicSharedMemorySize, FPS_SMEM);
    cudaFuncSetAttribute(knn_kernel,   cudaFuncAttributeMaxDynamicSharedMemorySize, KNN_SMEM);
    cudaFuncSetAttribute(gemm0_kernel, cudaFuncAttributeMaxDynamicSharedMemorySize, G0_SMEM);
    cudaFuncSetAttribute(gemm1_kernel, cudaFuncAttributeMaxDynamicSharedMemorySize, G1_SMEM);

    fps_kernel  <<<Bc*FPS_CLUS, 512, FPS_SMEM>>>(xyz, out);
    knn_kernel  <<<128, 256, KNN_SMEM>>>(xyz, out);
    gemm0_kernel<<<GBLKS, 256, G0_SMEM>>>(xyz, feat, w0, b0, out);
    stats_kernel<<<Cc, 256>>>(0, g0, be0);
    gemm1_kernel<<<GBLKS, 256, G1_SMEM>>>(w1, b1);
    stats_kernel<<<Cc, 256>>>(1, g1, be1);
    final_kernel<<<(Bc*Sc*Cc)/256, 256>>>(out);
}